// round 13
// baseline (speedup 1.0000x reference)
#include <cuda_runtime.h>
#include <math.h>

// Problem constants (fixed shapes from the reference)
#define N_ENT   14541
#define N_REL   237
#define M_EDGES 272115
#define D       256
#define BS      16
#define NT      4                       // entities per warp tile
#define OUT_ELEMS (N_ENT * BS)

typedef unsigned long long u64;

// Scratch (static device arrays; no runtime allocation)
__device__ float    g_sig[N_ENT * BS];
__device__ unsigned g_relmask[N_REL];

// acc += |e - x| * r on packed f32x2 pairs.
//   fma-pipe: FFMA2 (diff = x*(-1) + e), FFMA2 (acc += |diff|*r)
//   alu-pipe: and.b64 -> 2x LOP3 in-place on the register pair (NO movs).
__device__ __forceinline__ void term(u64& a, u64 e, u64 x, u64 r, u64 neg1) {
    asm("{\n\t"
        ".reg .b64 t;\n\t"
        "fma.rn.f32x2 t, %2, %3, %1;\n\t"
        "and.b64 t, t, 0x7FFFFFFF7FFFFFFF;\n\t"
        "fma.rn.f32x2 %0, t, %4, %0;\n\t"
        "}" : "+l"(a) : "l"(e), "l"(x), "l"(neg1), "l"(r));
}

__device__ __forceinline__ float pair_sum(u64 v) {
    float lo, hi;
    asm("mov.b64 {%0, %1}, %2;" : "=f"(lo), "=f"(hi) : "l"(v));
    return lo + hi;
}

// ---------------------------------------------------------------------------
// dist: sig[n][b] = sigmoid(12 - sum_d |rel[b,d]| * |emb[b,d] - all_emb[n,d]|)
//       with sig[source_idx[b]][b] = 0 (sigmoid(12-1e8) == 0 in fp32).
// One warp = NT=4 entities x all 16 batch items; lane owns d in
// {4L..4L+3} u {128+4L..128+4L+3}, processed as packed f32x2 pairs.
// Side jobs: zero `out`; block 0 builds the relation->batch bitmask.
// ---------------------------------------------------------------------------
__global__ void __launch_bounds__(256) dist_kernel(
    const float* __restrict__ emb,
    const float* __restrict__ all_emb,
    const float* __restrict__ tail_r,
    const int*   __restrict__ source_idx,
    const int*   __restrict__ relation_ids,
    float*       __restrict__ out)
{
    __shared__ __align__(16) float es[BS * D];   // emb[b][d]
    __shared__ __align__(16) float rs[BS * D];   // |tail_r[relation_ids[b]][d]|
    __shared__ int s_src[BS];

    const int tid  = threadIdx.x;
    const int lane = tid & 31;

    // Zero the output buffer (930 KB over 455 blocks, float2/thread).
    {
        const int i0 = (blockIdx.x * 256 + tid) * 2;
        if (i0 + 2 <= OUT_ELEMS)
            *(float2*)(out + i0) = make_float2(0.f, 0.f);
        else if (i0 < OUT_ELEMS)
            out[i0] = 0.f;
    }

    // Block 0: relation->batch bitmask for the edge kernel.
    if (blockIdx.x == 0 && tid < N_REL) {
        unsigned m = 0;
        #pragma unroll
        for (int b = 0; b < BS; b++)
            m |= (relation_ids[b] == tid) ? (1u << b) : 0u;
        g_relmask[tid] = m;
    }

    if (tid < BS) s_src[tid] = source_idx[tid];
    for (int i = tid; i < BS * D; i += 256) {
        int b = i >> 8;          // i / D
        int d = i & (D - 1);     // i % D
        es[i] = emb[i];
        rs[i] = fabsf(tail_r[relation_ids[b] * D + d]);
    }
    __syncthreads();

    const int warp = blockIdx.x * 8 + (tid >> 5);
    const int n0   = warp * NT;
    if (n0 >= N_ENT) return;

    const u64 neg1 = 0xBF800000BF800000ull;   // packed {-1.0f, -1.0f}

    // Preload all_emb rows as packed pairs (rows are 1KB-aligned; LDG.128).
    // xp[n][0..1] <- d {4L..4L+3}; xp[n][2..3] <- d {128+4L..128+4L+3}.
    u64 xp[NT][4];
    #pragma unroll
    for (int n = 0; n < NT; n++) {
        int nn = n0 + n; if (nn >= N_ENT) nn = N_ENT - 1;
        const ulonglong2* row = (const ulonglong2*)(all_emb + nn * D);
        ulonglong2 a = row[lane];
        ulonglong2 c = row[32 + lane];
        xp[n][0] = a.x; xp[n][1] = a.y;
        xp[n][2] = c.x; xp[n][3] = c.y;
    }

    u64 acc[NT * BS];
    #pragma unroll
    for (int i = 0; i < NT * BS; i++) acc[i] = 0ull;

    // es/rs viewed as 16B-aligned packed pairs: 64 ulonglong2 per b-row.
    const ulonglong2* es2 = (const ulonglong2*)es;
    const ulonglong2* rs2 = (const ulonglong2*)rs;

    #pragma unroll
    for (int b = 0; b < BS; b++) {
        ulonglong2 e01 = es2[b * 64 + lane];         // LDS.128
        ulonglong2 e23 = es2[b * 64 + 32 + lane];
        ulonglong2 r01 = rs2[b * 64 + lane];
        ulonglong2 r23 = rs2[b * 64 + 32 + lane];
        #pragma unroll
        for (int n = 0; n < NT; n++) {
            u64& a = acc[n * BS + b];
            term(a, e01.x, xp[n][0], r01.x, neg1);
            term(a, e01.y, xp[n][1], r01.y, neg1);
            term(a, e23.x, xp[n][2], r23.x, neg1);
            term(a, e23.y, xp[n][3], r23.y, neg1);
        }
    }

    // Fold packed pairs to scalars, then value-splitting butterfly:
    // 64 partials -> 62 shuffles; lane L ends with flat sums 2L and 2L+1,
    // where flat = n_local*16 + b.
    float sac[NT * BS];
    #pragma unroll
    for (int i = 0; i < NT * BS; i++) sac[i] = pair_sum(acc[i]);

    #pragma unroll
    for (int step = 0; step < 5; step++) {
        const int mask = 16 >> step;
        const int V    = 64 >> step;
        const bool hi  = (lane & mask) != 0;
        #pragma unroll
        for (int i = 0; i < V / 2; i++) {
            float send = hi ? sac[i]         : sac[i + V / 2];
            float keep = hi ? sac[i + V / 2] : sac[i];
            float other = __shfl_xor_sync(0xffffffffu, send, mask);
            sac[i] = keep + other;
        }
    }

    // Epilogue: mask + sigmoid, coalesced float2 store
    const int f  = 2 * lane;
    const int nn = n0 + (f >> 4);
    const int b  = f & 15;
    if (nn < N_ENT) {
        float s0 = 1.0f / (1.0f + __expf(sac[0] - 12.0f));
        float s1 = 1.0f / (1.0f + __expf(sac[1] - 12.0f));
        if (nn == s_src[b])     s0 = 0.0f;
        if (nn == s_src[b + 1]) s1 = 0.0f;
        *(float2*)(g_sig + nn * BS + b) = make_float2(s0, s1);
    }
}

// ---------------------------------------------------------------------------
// edge: one edge per thread. Coalesced rel load -> L1-resident bitmask probe;
// ~93% of threads exit immediately. Survivors gather sig[head][b] and
// atomically scatter-add onto out[b][tail]. (Measured 6.08us; unchanged.)
// ---------------------------------------------------------------------------
__global__ void __launch_bounds__(256, 8) edge_kernel(
    const int* __restrict__ heads,
    const int* __restrict__ tails,
    const int* __restrict__ rels,
    float*     __restrict__ out)
{
    const int i = blockIdx.x * 256 + threadIdx.x;
    if (i >= M_EDGES) return;

    const int r = __ldg(rels + i);
    unsigned m = g_relmask[r];
    if (!m) return;

    const int h = __ldg(heads + i);
    const int t = __ldg(tails + i);
    do {
        int b = __ffs(m) - 1;
        m &= m - 1;
        atomicAdd(out + b * N_ENT + t, g_sig[h * BS + b]);
    } while (m);
}

// ---------------------------------------------------------------------------
extern "C" void kernel_launch(void* const* d_in, const int* in_sizes, int n_in,
                              void* d_out, int out_size) {
    const float* emb          = (const float*)d_in[0];
    const float* all_emb      = (const float*)d_in[1];
    const float* tail_r       = (const float*)d_in[2];
    const int*   source_idx   = (const int*)  d_in[3];
    const int*   relation_ids = (const int*)  d_in[4];
    const int*   heads        = (const int*)  d_in[5];
    const int*   tails        = (const int*)  d_in[6];
    const int*   edge_rels    = (const int*)  d_in[7];
    float*       out          = (float*)d_out;

    const int warps  = (N_ENT + NT - 1) / NT;      // 3636
    const int blocks = (warps + 7) / 8;            // 455
    dist_kernel<<<blocks, 256>>>(emb, all_emb, tail_r, source_idx,
                                 relation_ids, out);

    const int eblocks = (M_EDGES + 255) / 256;     // 1063
    edge_kernel<<<eblocks, 256>>>(heads, tails, edge_rels, out);
}